// round 1
// baseline (speedup 1.0000x reference)
#include <cuda_runtime.h>

#define NNODES 100000
#define NEDGES 1600000
#define NREL   12
#define NPAIR  4096

// Scratch (device globals; no allocation allowed).
__device__ __align__(256) float g_t[(size_t)NREL * NNODES * 128];   // 614 MB
__device__ __align__(256) float g_aggA[(size_t)NNODES * 128];       // 51 MB
__device__ __align__(256) float g_aggB[(size_t)NNODES * 128];       // 51 MB
__device__ __align__(256) float g_hd[(size_t)NNODES * 2];

// ---------------------------------------------------------------------------
// Transform: out[r, n, :] = act(in[n, :]) @ W[r]  (+ bias)
// act = relu if RELU_IN. Grid: (node_tiles, R). 256 threads.
// A tile stored transposed in smem (k-major, padded) -> broadcast LDS.128.
// ---------------------------------------------------------------------------
template<int DIN, int DOUT, bool RELU_IN, bool HAS_BIAS>
__global__ __launch_bounds__(256) void transform_kernel(
    const float* __restrict__ in,    // [N, DIN]
    const float* __restrict__ W,     // [R, DIN, DOUT]
    const float* __restrict__ bias,  // [DOUT] or null
    float* __restrict__ out,         // [R, N, DOUT] with stride rStride per r
    int nNodes, long long rStride)
{
    constexpr int BM   = 64;          // nodes per block
    constexpr int OX   = DOUT / 4;    // thread cols (each covers 4 outputs)
    constexpr int MY   = 256 / OX;    // thread rows
    constexpr int MPT  = BM / MY;     // nodes per thread (8 for DOUT=128, 4 for 64)
    constexpr int SROW = BM + 4;      // padded smem row stride

    __shared__ float shA[DIN * SROW];

    const int base = blockIdx.x * BM;
    const int r    = blockIdx.y;
    const int tid  = threadIdx.x;

    // Load A tile (transposed), apply relu on read if requested.
    for (int idx = tid; idx < BM * DIN; idx += 256) {
        int m = idx / DIN;
        int k = idx - m * DIN;
        int n = base + m;
        float v = (n < nNodes) ? in[(size_t)n * DIN + k] : 0.0f;
        if (RELU_IN) v = fmaxf(v, 0.0f);
        shA[k * SROW + m] = v;
    }
    __syncthreads();

    const int o0 = (tid % OX) * 4;
    const int m0 = (tid / OX) * MPT;
    const float* Wr = W + (size_t)r * DIN * DOUT;

    float acc[MPT][4];
    #pragma unroll
    for (int mi = 0; mi < MPT; mi++) {
        acc[mi][0] = 0.f; acc[mi][1] = 0.f; acc[mi][2] = 0.f; acc[mi][3] = 0.f;
    }

    #pragma unroll 4
    for (int k = 0; k < DIN; k++) {
        float4 wv = __ldg((const float4*)(Wr + (size_t)k * DOUT + o0));
        #pragma unroll
        for (int mq = 0; mq < MPT; mq += 4) {
            float4 av = *(const float4*)(&shA[k * SROW + m0 + mq]);
            acc[mq + 0][0] += av.x * wv.x;
            acc[mq + 0][1] += av.x * wv.y;
            acc[mq + 0][2] += av.x * wv.z;
            acc[mq + 0][3] += av.x * wv.w;
            acc[mq + 1][0] += av.y * wv.x;
            acc[mq + 1][1] += av.y * wv.y;
            acc[mq + 1][2] += av.y * wv.z;
            acc[mq + 1][3] += av.y * wv.w;
            acc[mq + 2][0] += av.z * wv.x;
            acc[mq + 2][1] += av.z * wv.y;
            acc[mq + 2][2] += av.z * wv.z;
            acc[mq + 2][3] += av.z * wv.w;
            acc[mq + 3][0] += av.w * wv.x;
            acc[mq + 3][1] += av.w * wv.y;
            acc[mq + 3][2] += av.w * wv.z;
            acc[mq + 3][3] += av.w * wv.w;
        }
    }

    float4 bv = make_float4(0.f, 0.f, 0.f, 0.f);
    if (HAS_BIAS) bv = __ldg((const float4*)(bias + o0));

    float* outr = out + (size_t)r * rStride;
    #pragma unroll
    for (int mi = 0; mi < MPT; mi++) {
        int n = base + m0 + mi;
        if (n < nNodes) {
            float4 v = make_float4(acc[mi][0] + bv.x, acc[mi][1] + bv.y,
                                   acc[mi][2] + bv.z, acc[mi][3] + bv.w);
            *(float4*)(outr + (size_t)n * DOUT + o0) = v;
        }
    }
}

// ---------------------------------------------------------------------------
// Edge scatter: agg[dst] += t[etype, src, :]. One warp per edge.
// agg is L2-resident (51 MB); uses float4 atomicAdd (sm_90+).
// ---------------------------------------------------------------------------
__global__ __launch_bounds__(256) void edge_kernel(
    const int* __restrict__ etypes, const int* __restrict__ src,
    const int* __restrict__ dst, const float* __restrict__ t,
    float* __restrict__ agg, int E, int nNodes, int dout)
{
    int warp = blockIdx.x * (blockDim.x >> 5) + (threadIdx.x >> 5);
    int lane = threadIdx.x & 31;
    if (warp >= E) return;

    int et = etypes[warp];
    int s  = src[warp];
    int d  = dst[warp];

    int nvec = dout >> 2;
    if (lane < nvec) {
        const float4* trow = (const float4*)(t + ((size_t)et * nNodes + s) * dout);
        float4 v = __ldg(trow + lane);
        float4* arow = (float4*)(agg + (size_t)d * dout);
        atomicAdd(arow + lane, v);
    }
}

// ---------------------------------------------------------------------------
// Final dense: hd[n, :2] = relu(agg[n, :64]) @ Wd + bd
// ---------------------------------------------------------------------------
__global__ __launch_bounds__(256) void dense_kernel(
    const float* __restrict__ agg, const float* __restrict__ Wd,
    const float* __restrict__ bd, float* __restrict__ hd, int nNodes)
{
    int n = blockIdx.x * blockDim.x + threadIdx.x;
    if (n >= nNodes) return;
    float a0 = bd[0], a1 = bd[1];
    const float4* row = (const float4*)(agg + (size_t)n * 64);
    #pragma unroll
    for (int kq = 0; kq < 16; kq++) {
        float4 v = __ldg(row + kq);
        float x;
        int k = kq * 4;
        x = fmaxf(v.x, 0.f); a0 += x * Wd[(k + 0) * 2]; a1 += x * Wd[(k + 0) * 2 + 1];
        x = fmaxf(v.y, 0.f); a0 += x * Wd[(k + 1) * 2]; a1 += x * Wd[(k + 1) * 2 + 1];
        x = fmaxf(v.z, 0.f); a0 += x * Wd[(k + 2) * 2]; a1 += x * Wd[(k + 2) * 2 + 1];
        x = fmaxf(v.w, 0.f); a0 += x * Wd[(k + 3) * 2]; a1 += x * Wd[(k + 3) * 2 + 1];
    }
    hd[(size_t)n * 2]     = a0;
    hd[(size_t)n * 2 + 1] = a1;
}

// ---------------------------------------------------------------------------
// Edge-pair gather: out1[p] = (hd[u1]+hd[v1])*0.5 ; out2[p] = (hd[u2]+hd[v2])*0.5
// out layout: [0, 2P) = out1, [2P, 4P) = out2 (row-major (P,2) each).
// ---------------------------------------------------------------------------
__global__ void gather_kernel(const int* __restrict__ ei,
                              const float* __restrict__ hd,
                              float* __restrict__ out, int P)
{
    int p = blockIdx.x * blockDim.x + threadIdx.x;
    if (p >= P) return;
    int4 idx = ((const int4*)ei)[p];
    float2 a = ((const float2*)hd)[idx.x];
    float2 b = ((const float2*)hd)[idx.y];
    float2 c = ((const float2*)hd)[idx.z];
    float2 d = ((const float2*)hd)[idx.w];
    out[(size_t)p * 2]             = (a.x + b.x) * 0.5f;
    out[(size_t)p * 2 + 1]         = (a.y + b.y) * 0.5f;
    out[(size_t)2 * P + p * 2]     = (c.x + d.x) * 0.5f;
    out[(size_t)2 * P + p * 2 + 1] = (c.y + d.y) * 0.5f;
}

extern "C" void kernel_launch(void* const* d_in, const int* in_sizes, int n_in,
                              void* d_out, int out_size)
{
    const float* h   = (const float*)d_in[0];
    const int*   src = (const int*)d_in[1];
    const int*   dst = (const int*)d_in[2];
    const int*   ety = (const int*)d_in[3];
    const int*   ei  = (const int*)d_in[4];
    const float* W0 = (const float*)d_in[5],  *L0 = (const float*)d_in[6],  *b0 = (const float*)d_in[7];
    const float* W1 = (const float*)d_in[8],  *L1 = (const float*)d_in[9],  *b1 = (const float*)d_in[10];
    const float* W2 = (const float*)d_in[11], *L2 = (const float*)d_in[12], *b2 = (const float*)d_in[13];
    const float* W3 = (const float*)d_in[14], *L3 = (const float*)d_in[15], *b3 = (const float*)d_in[16];
    const float* Wd = (const float*)d_in[17], *bd = (const float*)d_in[18];
    float* out = (float*)d_out;

    float *t, *aggA, *aggB, *hd;
    cudaGetSymbolAddress((void**)&t,    g_t);
    cudaGetSymbolAddress((void**)&aggA, g_aggA);
    cudaGetSymbolAddress((void**)&aggB, g_aggB);
    cudaGetSymbolAddress((void**)&hd,   g_hd);

    const int nTiles = (NNODES + 63) / 64;
    dim3 gridT(nTiles, NREL);
    dim3 gridS(nTiles, 1);
    const int egrid = (NEDGES + 7) / 8;   // 8 edges (warps) per 256-thread block

    // Layer 0: 16 -> 128 (no relu on input h)
    transform_kernel<16, 128, false, false><<<gridT, 256>>>(h, W0, nullptr, t, NNODES, (long long)NNODES * 128);
    transform_kernel<16, 128, false, true ><<<gridS, 256>>>(h, L0, b0, aggA, NNODES, 0);
    edge_kernel<<<egrid, 256>>>(ety, src, dst, t, aggA, NEDGES, NNODES, 128);

    // Layer 1: 128 -> 128 (relu fused into reads of aggA)
    transform_kernel<128, 128, true, false><<<gridT, 256>>>(aggA, W1, nullptr, t, NNODES, (long long)NNODES * 128);
    transform_kernel<128, 128, true, true ><<<gridS, 256>>>(aggA, L1, b1, aggB, NNODES, 0);
    edge_kernel<<<egrid, 256>>>(ety, src, dst, t, aggB, NEDGES, NNODES, 128);

    // Layer 2: 128 -> 128
    transform_kernel<128, 128, true, false><<<gridT, 256>>>(aggB, W2, nullptr, t, NNODES, (long long)NNODES * 128);
    transform_kernel<128, 128, true, true ><<<gridS, 256>>>(aggB, L2, b2, aggA, NNODES, 0);
    edge_kernel<<<egrid, 256>>>(ety, src, dst, t, aggA, NEDGES, NNODES, 128);

    // Layer 3: 128 -> 64
    transform_kernel<128, 64, true, false><<<gridT, 256>>>(aggA, W3, nullptr, t, NNODES, (long long)NNODES * 64);
    transform_kernel<128, 64, true, true ><<<gridS, 256>>>(aggA, L3, b3, aggB, NNODES, 0);
    edge_kernel<<<egrid, 256>>>(ety, src, dst, t, aggB, NEDGES, NNODES, 64);

    // Final dense + pair gather
    dense_kernel<<<(NNODES + 255) / 256, 256>>>(aggB, Wd, bd, hd, NNODES);
    gather_kernel<<<(NPAIR + 255) / 256, 256>>>(ei, hd, out, NPAIR);
}

// round 3
// speedup vs baseline: 1.6522x; 1.6522x over previous
#include <cuda_runtime.h>
#include <cuda_bf16.h>
#include <cstdint>

#define NNODES 100000
#define NPAD   100096          // 782 * 128
#define NT     782
#define NEDGES 1600000
#define NREL   12
#define NMAT   13              // 12 relations + self-loop
#define NPAIR  4096

// ---------------------------------------------------------------------------
// Scratch (device globals; no allocation allowed).
// ---------------------------------------------------------------------------
__device__ __align__(1024) float          g_t[(size_t)NMAT * NPAD * 128];   // 666 MB
__device__ __align__(1024) __nv_bfloat16  g_asplit[(size_t)NPAD * 256];     // [n][2*DIN]
__device__ __align__(1024) __nv_bfloat16  g_wsplit[(size_t)NMAT * 256 * 128];
__device__ __align__(1024) float          g_aggA[(size_t)NPAD * 128];
__device__ __align__(1024) float          g_aggB[(size_t)NPAD * 128];
__device__ __align__(1024) float          g_hd[(size_t)NPAD * 2];

// ---------------------------------------------------------------------------
// PTX helpers (portable sm_80+ path: cp.async, ldmatrix, mma.sync)
// ---------------------------------------------------------------------------
__device__ __forceinline__ uint32_t smem_u32(const void* p) {
    uint32_t a;
    asm("{ .reg .u64 t; cvta.to.shared.u64 t, %1; cvt.u32.u64 %0, t; }" : "=r"(a) : "l"(p));
    return a;
}

#define CPASYNC16(saddr, gptr) \
    asm volatile("cp.async.cg.shared.global [%0], [%1], 16;" :: "r"(saddr), "l"(gptr))
#define CPASYNC_COMMIT() asm volatile("cp.async.commit_group;")
#define CPASYNC_WAIT0()  asm volatile("cp.async.wait_group 0;")
#define CPASYNC_WAIT1()  asm volatile("cp.async.wait_group 1;")

#define LDSM_X4(r0, r1, r2, r3, addr) \
    asm volatile("ldmatrix.sync.aligned.m8n8.x4.shared.b16 {%0,%1,%2,%3}, [%4];" \
        : "=r"(r0), "=r"(r1), "=r"(r2), "=r"(r3) : "r"(addr))
#define LDSM_X4_T(r0, r1, r2, r3, addr) \
    asm volatile("ldmatrix.sync.aligned.m8n8.x4.trans.shared.b16 {%0,%1,%2,%3}, [%4];" \
        : "=r"(r0), "=r"(r1), "=r"(r2), "=r"(r3) : "r"(addr))

#define MMA_BF16(c, a, b0, b1) \
    asm volatile("mma.sync.aligned.m16n8k16.row.col.f32.bf16.bf16.f32 " \
        "{%0,%1,%2,%3}, {%4,%5,%6,%7}, {%8,%9}, {%0,%1,%2,%3};" \
        : "+f"((c)[0]), "+f"((c)[1]), "+f"((c)[2]), "+f"((c)[3]) \
        : "r"((a)[0]), "r"((a)[1]), "r"((a)[2]), "r"((a)[3]), "r"(b0), "r"(b1))

__device__ __forceinline__ uint32_t bfbits(float x) {
    return (uint32_t)__bfloat16_as_ushort(__float2bfloat16_rn(x));
}

// ---------------------------------------------------------------------------
// prep_act: fp32 [N, DIN] -> bf16 [NPAD, 2*DIN] = [hi | lo], padded rows zero.
// ---------------------------------------------------------------------------
template<int DIN, bool RELU>
__global__ __launch_bounds__(256) void prep_act_kernel(
    const float* __restrict__ in, __nv_bfloat16* __restrict__ out)
{
    constexpr int KP = 2 * DIN;
    int idx = blockIdx.x * 256 + threadIdx.x;
    if (idx >= NPAD * (DIN / 4)) return;
    int n  = idx / (DIN / 4);
    int k0 = (idx % (DIN / 4)) * 4;
    float4 v = make_float4(0.f, 0.f, 0.f, 0.f);
    if (n < NNODES) v = __ldg((const float4*)(in + (size_t)n * DIN + k0));
    if (RELU) {
        v.x = fmaxf(v.x, 0.f); v.y = fmaxf(v.y, 0.f);
        v.z = fmaxf(v.z, 0.f); v.w = fmaxf(v.w, 0.f);
    }
    float xs[4] = {v.x, v.y, v.z, v.w};
    uint32_t hb[4], lb[4];
    #pragma unroll
    for (int j = 0; j < 4; j++) {
        __nv_bfloat16 h = __float2bfloat16_rn(xs[j]);
        hb[j] = (uint32_t)__bfloat16_as_ushort(h);
        lb[j] = bfbits(xs[j] - __bfloat162float(h));
    }
    *(uint2*)(out + (size_t)n * KP + k0) =
        make_uint2(hb[0] | (hb[1] << 16), hb[2] | (hb[3] << 16));
    *(uint2*)(out + (size_t)n * KP + DIN + k0) =
        make_uint2(lb[0] | (lb[1] << 16), lb[2] | (lb[3] << 16));
}

// ---------------------------------------------------------------------------
// prep_w: W [R, DIN, DOUT] + L [DIN, DOUT] -> bf16 [NMAT][2*DIN][DOUT]
// rows [0,DIN) = hi, rows [DIN,2*DIN) = lo.
// ---------------------------------------------------------------------------
template<int DIN, int DOUT>
__global__ __launch_bounds__(256) void prep_w_kernel(
    const float* __restrict__ W, const float* __restrict__ L,
    __nv_bfloat16* __restrict__ out)
{
    int idx = blockIdx.x * 256 + threadIdx.x;
    if (idx >= NMAT * DIN * (DOUT / 4)) return;
    int m   = idx / (DIN * (DOUT / 4));
    int rem = idx % (DIN * (DOUT / 4));
    int k   = rem / (DOUT / 4);
    int n0  = (rem % (DOUT / 4)) * 4;
    const float* src = (m < NREL) ? (W + (size_t)m * DIN * DOUT) : L;
    float4 v = __ldg((const float4*)(src + (size_t)k * DOUT + n0));
    float xs[4] = {v.x, v.y, v.z, v.w};
    uint32_t hb[4], lb[4];
    #pragma unroll
    for (int j = 0; j < 4; j++) {
        __nv_bfloat16 h = __float2bfloat16_rn(xs[j]);
        hb[j] = (uint32_t)__bfloat16_as_ushort(h);
        lb[j] = bfbits(xs[j] - __bfloat162float(h));
    }
    __nv_bfloat16* base = out + (size_t)m * (2 * DIN) * DOUT;
    *(uint2*)(base + (size_t)k * DOUT + n0) =
        make_uint2(hb[0] | (hb[1] << 16), hb[2] | (hb[3] << 16));
    *(uint2*)(base + (size_t)(DIN + k) * DOUT + n0) =
        make_uint2(lb[0] | (lb[1] << 16), lb[2] | (lb[3] << 16));
}

// ---------------------------------------------------------------------------
// GEMM via mma.sync bf16: for each 128-node tile, for 13 matrices:
//   t[r,tile] = Ah*Wh + Ah*Wl + Al*Wh   (fp32 accum)
// One K-loop over 3*DIN with segment index mapping. W double-buffered.
// 8 warps: warp (wid%4) -> m block of 32, (wid/4) -> n block of DOUT/2.
// ---------------------------------------------------------------------------
template<int DIN, int DOUT>
__global__ __launch_bounds__(256) void gemm_mma_kernel(
    const __nv_bfloat16* __restrict__ aimg,   // [NPAD][2*DIN]
    const __nv_bfloat16* __restrict__ wimg,   // [NMAT][2*DIN][DOUT]
    float* __restrict__ t)
{
    constexpr int KP     = 2 * DIN;
    constexpr int KC16   = DIN / 16;
    constexpr int NCH    = 3 * KC16;
    constexpr int LDA    = KP + 8;      // halves; +16B pad -> conflict-free ldmatrix
    constexpr int LDW    = DOUT + 8;
    constexpr int A_BYTES = 128 * LDA * 2;
    constexpr int W_BYTES = KP * LDW * 2;
    constexpr int NTILES  = DOUT / 16;  // n-tiles (of 8) per warp

    extern __shared__ unsigned char sm[];
    const uint32_t smb  = smem_u32(sm);
    const uint32_t Wsm0 = smb + A_BYTES;

    const int tid  = threadIdx.x;
    const int wid  = tid >> 5;
    const int lane = tid & 31;
    const int tile = blockIdx.x;
    const int m0   = (wid & 3) * 32;
    const int n0   = (wid >> 2) * (DOUT / 2);

    // Load A tile + W0 (group 0)
    const __nv_bfloat16* ga = aimg + (size_t)tile * 128 * KP;
    for (int i = tid; i < 128 * (KP / 8); i += 256) {
        int rr = i / (KP / 8), j = (i % (KP / 8)) * 8;
        CPASYNC16(smb + (rr * LDA + j) * 2, ga + (size_t)rr * KP + j);
    }
    for (int i = tid; i < KP * (DOUT / 8); i += 256) {
        int rr = i / (DOUT / 8), j = (i % (DOUT / 8)) * 8;
        CPASYNC16(Wsm0 + (rr * LDW + j) * 2, wimg + (size_t)rr * DOUT + j);
    }
    CPASYNC_COMMIT();

    for (int r = 0; r < NMAT; ++r) {
        // Prefetch W[r+1] into the other buffer.
        if (r + 1 < NMAT) {
            uint32_t wb = Wsm0 + (uint32_t)((r + 1) & 1) * W_BYTES;
            const __nv_bfloat16* gw = wimg + (size_t)(r + 1) * KP * DOUT;
            for (int i = tid; i < KP * (DOUT / 8); i += 256) {
                int rr = i / (DOUT / 8), j = (i % (DOUT / 8)) * 8;
                CPASYNC16(wb + (rr * LDW + j) * 2, gw + (size_t)rr * DOUT + j);
            }
            CPASYNC_COMMIT();
            CPASYNC_WAIT1();       // W_r (and A) resident; W_{r+1} may fly
        } else {
            CPASYNC_WAIT0();
        }
        __syncthreads();

        const uint32_t wb = Wsm0 + (uint32_t)(r & 1) * W_BYTES;
        float acc[2][NTILES][4];
        #pragma unroll
        for (int mt = 0; mt < 2; mt++)
            #pragma unroll
            for (int nt = 0; nt < NTILES; nt++) {
                acc[mt][nt][0] = 0.f; acc[mt][nt][1] = 0.f;
                acc[mt][nt][2] = 0.f; acc[mt][nt][3] = 0.f;
            }

        #pragma unroll
        for (int c = 0; c < NCH; ++c) {
            const int seg  = c / KC16;
            const int kk   = (c % KC16) * 16;
            const int aoff = (seg == 2 ? DIN : 0) + kk;   // Ah,Ah,Al
            const int wrow = (seg == 1 ? DIN : 0) + kk;   // Wh,Wl,Wh

            uint32_t a[2][4];
            #pragma unroll
            for (int mt = 0; mt < 2; mt++) {
                uint32_t addr = smb +
                    (uint32_t)(((m0 + mt * 16 + (lane & 15)) * LDA + aoff) * 2) +
                    (uint32_t)((lane >> 4) * 16);
                LDSM_X4(a[mt][0], a[mt][1], a[mt][2], a[mt][3], addr);
            }
            uint32_t b[NTILES][2];
            #pragma unroll
            for (int np = 0; np < NTILES / 2; np++) {
                uint32_t addr = wb +
                    (uint32_t)(((wrow + (lane & 15)) * LDW + n0 + np * 16) * 2) +
                    (uint32_t)((lane >> 4) * 16);
                LDSM_X4_T(b[2 * np][0], b[2 * np][1],
                          b[2 * np + 1][0], b[2 * np + 1][1], addr);
            }
            #pragma unroll
            for (int mt = 0; mt < 2; mt++)
                #pragma unroll
                for (int nt = 0; nt < NTILES; nt++)
                    MMA_BF16(acc[mt][nt], a[mt], b[nt][0], b[nt][1]);
        }
        __syncthreads();   // all warps done reading smem before next prefetch reuses it

        // Epilogue: write t[r]
        float* tr = t + (size_t)r * NPAD * DOUT + (size_t)tile * 128 * DOUT;
        #pragma unroll
        for (int mt = 0; mt < 2; mt++) {
            int row = m0 + mt * 16 + (lane >> 2);
            float* p = tr + (size_t)row * DOUT + n0 + (lane & 3) * 2;
            #pragma unroll
            for (int nt = 0; nt < NTILES; nt++) {
                *(float2*)(p + nt * 8)            = make_float2(acc[mt][nt][0], acc[mt][nt][1]);
                *(float2*)(p + 8 * DOUT + nt * 8) = make_float2(acc[mt][nt][2], acc[mt][nt][3]);
            }
        }
    }
}

// ---------------------------------------------------------------------------
// init_agg: agg[n,:] = t[12][n,:] + bias
// ---------------------------------------------------------------------------
template<int DOUT>
__global__ __launch_bounds__(256) void init_agg_kernel(
    const float* __restrict__ t12, const float* __restrict__ b,
    float* __restrict__ agg)
{
    int idx = blockIdx.x * blockDim.x + threadIdx.x;
    if (idx >= NNODES * (DOUT / 4)) return;
    int n = idx / (DOUT / 4);
    int c = (idx % (DOUT / 4)) * 4;
    float4 v  = __ldg((const float4*)(t12 + (size_t)n * DOUT + c));
    float4 bv = __ldg((const float4*)(b + c));
    v.x += bv.x; v.y += bv.y; v.z += bv.z; v.w += bv.w;
    *(float4*)(agg + (size_t)n * DOUT + c) = v;
}

// ---------------------------------------------------------------------------
// Edge scatter: agg[dst] += t[etype, src, :]. One warp per edge, float4 atomics.
// ---------------------------------------------------------------------------
__global__ __launch_bounds__(256) void edge_kernel(
    const int* __restrict__ etypes, const int* __restrict__ src,
    const int* __restrict__ dst, const float* __restrict__ t,
    float* __restrict__ agg, int E, int dout)
{
    int warp = blockIdx.x * (blockDim.x >> 5) + (threadIdx.x >> 5);
    int lane = threadIdx.x & 31;
    if (warp >= E) return;
    int et = etypes[warp], s = src[warp], d = dst[warp];
    int nvec = dout >> 2;
    if (lane < nvec) {
        const float4* trow = (const float4*)(t + ((size_t)et * NPAD + s) * dout);
        float4 v = __ldg(trow + lane);
        atomicAdd(((float4*)(agg + (size_t)d * dout)) + lane, v);
    }
}

// ---------------------------------------------------------------------------
// Final dense + pair gather
// ---------------------------------------------------------------------------
__global__ __launch_bounds__(256) void dense_kernel(
    const float* __restrict__ agg, const float* __restrict__ Wd,
    const float* __restrict__ bd, float* __restrict__ hd, int nNodes)
{
    int n = blockIdx.x * blockDim.x + threadIdx.x;
    if (n >= nNodes) return;
    float a0 = bd[0], a1 = bd[1];
    const float4* row = (const float4*)(agg + (size_t)n * 64);
    #pragma unroll
    for (int kq = 0; kq < 16; kq++) {
        float4 v = __ldg(row + kq);
        float x; int k = kq * 4;
        x = fmaxf(v.x, 0.f); a0 += x * Wd[(k + 0) * 2]; a1 += x * Wd[(k + 0) * 2 + 1];
        x = fmaxf(v.y, 0.f); a0 += x * Wd[(k + 1) * 2]; a1 += x * Wd[(k + 1) * 2 + 1];
        x = fmaxf(v.z, 0.f); a0 += x * Wd[(k + 2) * 2]; a1 += x * Wd[(k + 2) * 2 + 1];
        x = fmaxf(v.w, 0.f); a0 += x * Wd[(k + 3) * 2]; a1 += x * Wd[(k + 3) * 2 + 1];
    }
    hd[(size_t)n * 2]     = a0;
    hd[(size_t)n * 2 + 1] = a1;
}

__global__ void gather_kernel(const int* __restrict__ ei,
                              const float* __restrict__ hd,
                              float* __restrict__ out, int P)
{
    int p = blockIdx.x * blockDim.x + threadIdx.x;
    if (p >= P) return;
    int4 idx = ((const int4*)ei)[p];
    float2 a = ((const float2*)hd)[idx.x];
    float2 b = ((const float2*)hd)[idx.y];
    float2 c = ((const float2*)hd)[idx.z];
    float2 d = ((const float2*)hd)[idx.w];
    out[(size_t)p * 2]             = (a.x + b.x) * 0.5f;
    out[(size_t)p * 2 + 1]         = (a.y + b.y) * 0.5f;
    out[(size_t)2 * P + p * 2]     = (c.x + d.x) * 0.5f;
    out[(size_t)2 * P + p * 2 + 1] = (c.y + d.y) * 0.5f;
}

// ---------------------------------------------------------------------------
// Host launcher
// ---------------------------------------------------------------------------
extern "C" void kernel_launch(void* const* d_in, const int* in_sizes, int n_in,
                              void* d_out, int out_size)
{
    const float* h   = (const float*)d_in[0];
    const int*   src = (const int*)d_in[1];
    const int*   dst = (const int*)d_in[2];
    const int*   ety = (const int*)d_in[3];
    const int*   ei  = (const int*)d_in[4];
    const float* W0 = (const float*)d_in[5],  *L0 = (const float*)d_in[6],  *b0 = (const float*)d_in[7];
    const float* W1 = (const float*)d_in[8],  *L1 = (const float*)d_in[9],  *b1 = (const float*)d_in[10];
    const float* W2 = (const float*)d_in[11], *L2 = (const float*)d_in[12], *b2 = (const float*)d_in[13];
    const float* W3 = (const float*)d_in[14], *L3 = (const float*)d_in[15], *b3 = (const float*)d_in[16];
    const float* Wd = (const float*)d_in[17], *bd = (const float*)d_in[18];
    float* out = (float*)d_out;

    float *t, *aggA, *aggB, *hd;
    __nv_bfloat16 *as, *ws;
    cudaGetSymbolAddress((void**)&t,    g_t);
    cudaGetSymbolAddress((void**)&as,   g_asplit);
    cudaGetSymbolAddress((void**)&ws,   g_wsplit);
    cudaGetSymbolAddress((void**)&aggA, g_aggA);
    cudaGetSymbolAddress((void**)&aggB, g_aggB);
    cudaGetSymbolAddress((void**)&hd,   g_hd);

    // Dynamic smem: A tile + 2 W buffers (padded rows)
    const int SM_16_128  = 128 * (32 + 8) * 2  + 2 * (32 * (128 + 8) * 2);   // 27648
    const int SM_128_128 = 128 * (256 + 8) * 2 + 2 * (256 * (128 + 8) * 2);  // 206848
    const int SM_128_64  = 128 * (256 + 8) * 2 + 2 * (256 * (64 + 8) * 2);   // 141312

    cudaFuncSetAttribute(gemm_mma_kernel<16, 128>,  cudaFuncAttributeMaxDynamicSharedMemorySize, SM_16_128);
    cudaFuncSetAttribute(gemm_mma_kernel<128, 128>, cudaFuncAttributeMaxDynamicSharedMemorySize, SM_128_128);
    cudaFuncSetAttribute(gemm_mma_kernel<128, 64>,  cudaFuncAttributeMaxDynamicSharedMemorySize, SM_128_64);

    const int egrid = (NEDGES + 7) / 8;

    // ---- Layer 0: 16 -> 128 ----
    prep_w_kernel<16, 128><<<(NMAT * 16 * 32 + 255) / 256, 256>>>(W0, L0, ws);
    prep_act_kernel<16, false><<<(NPAD * 4 + 255) / 256, 256>>>(h, as);
    gemm_mma_kernel<16, 128><<<NT, 256, SM_16_128>>>(as, ws, t);
    init_agg_kernel<128><<<(NNODES * 32 + 255) / 256, 256>>>(t + (size_t)12 * NPAD * 128, b0, aggA);
    edge_kernel<<<egrid, 256>>>(ety, src, dst, t, aggA, NEDGES, 128);

    // ---- Layer 1: 128 -> 128 ----
    prep_w_kernel<128, 128><<<(NMAT * 128 * 32 + 255) / 256, 256>>>(W1, L1, ws);
    prep_act_kernel<128, true><<<(NPAD * 32 + 255) / 256, 256>>>(aggA, as);
    gemm_mma_kernel<128, 128><<<NT, 256, SM_128_128>>>(as, ws, t);
    init_agg_kernel<128><<<(NNODES * 32 + 255) / 256, 256>>>(t + (size_t)12 * NPAD * 128, b1, aggB);
    edge_kernel<<<egrid, 256>>>(ety, src, dst, t, aggB, NEDGES, 128);

    // ---- Layer 2: 128 -> 128 ----
    prep_w_kernel<128, 128><<<(NMAT * 128 * 32 + 255) / 256, 256>>>(W2, L2, ws);
    prep_act_kernel<128, true><<<(NPAD * 32 + 255) / 256, 256>>>(aggB, as);
    gemm_mma_kernel<128, 128><<<NT, 256, SM_128_128>>>(as, ws, t);
    init_agg_kernel<128><<<(NNODES * 32 + 255) / 256, 256>>>(t + (size_t)12 * NPAD * 128, b2, aggA);
    edge_kernel<<<egrid, 256>>>(ety, src, dst, t, aggA, NEDGES, 128);

    // ---- Layer 3: 128 -> 64 ----
    prep_w_kernel<128, 64><<<(NMAT * 128 * 16 + 255) / 256, 256>>>(W3, L3, ws);
    prep_act_kernel<128, true><<<(NPAD * 32 + 255) / 256, 256>>>(aggA, as);
    gemm_mma_kernel<128, 64><<<NT, 256, SM_128_64>>>(as, ws, t);
    init_agg_kernel<64><<<(NNODES * 16 + 255) / 256, 256>>>(t + (size_t)12 * NPAD * 64, b3, aggB);
    edge_kernel<<<egrid, 256>>>(ety, src, dst, t, aggB, NEDGES, 64);

    // ---- Final dense + pair gather ----
    dense_kernel<<<(NNODES + 255) / 256, 256>>>(aggB, Wd, bd, hd, NNODES);
    gather_kernel<<<(NPAIR + 255) / 256, 256>>>(ei, hd, out, NPAIR);
}

// round 4
// speedup vs baseline: 1.7118x; 1.0360x over previous
#include <cuda_runtime.h>
#include <cuda_bf16.h>
#include <cstdint>

#define NNODES 100000
#define NPAD   100096          // 782 * 128
#define NT     782
#define NEDGES 1600000
#define NREL   12
#define NMAT   13              // 12 relations + self-loop
#define NPAIR  4096
#define NBINS  (NT * NREL)     // 9384

// ---------------------------------------------------------------------------
// Scratch (device globals; no allocation allowed).
// ---------------------------------------------------------------------------
__device__ __align__(1024) __nv_bfloat16  g_asplit[(size_t)NPAD * 256];       // [n][2*DIN]
__device__ __align__(1024) __nv_bfloat16  g_wsplit[(size_t)NMAT * 256 * 128];
__device__ __align__(1024) float          g_agg[(size_t)NPAD * 128];
__device__ __align__(1024) float          g_hd[(size_t)NPAD * 2];
__device__ __align__(1024) int            g_count[NBINS];
__device__ __align__(1024) int            g_binoff[NBINS + 1];
__device__ __align__(1024) int            g_cursor[NBINS];
__device__ __align__(1024) int            g_sorted[NEDGES];   // (srcloc<<17)|dst

// ---------------------------------------------------------------------------
// PTX helpers (portable sm_80+ path: cp.async, ldmatrix, mma.sync)
// ---------------------------------------------------------------------------
__device__ __forceinline__ uint32_t smem_u32(const void* p) {
    uint32_t a;
    asm("{ .reg .u64 t; cvta.to.shared.u64 t, %1; cvt.u32.u64 %0, t; }" : "=r"(a) : "l"(p));
    return a;
}

#define CPASYNC16(saddr, gptr) \
    asm volatile("cp.async.cg.shared.global [%0], [%1], 16;" :: "r"(saddr), "l"(gptr))
#define CPASYNC_COMMIT() asm volatile("cp.async.commit_group;")
#define CPASYNC_WAIT0()  asm volatile("cp.async.wait_group 0;")

#define LDSM_X4(r0, r1, r2, r3, addr) \
    asm volatile("ldmatrix.sync.aligned.m8n8.x4.shared.b16 {%0,%1,%2,%3}, [%4];" \
        : "=r"(r0), "=r"(r1), "=r"(r2), "=r"(r3) : "r"(addr))
#define LDSM_X4_T(r0, r1, r2, r3, addr) \
    asm volatile("ldmatrix.sync.aligned.m8n8.x4.trans.shared.b16 {%0,%1,%2,%3}, [%4];" \
        : "=r"(r0), "=r"(r1), "=r"(r2), "=r"(r3) : "r"(addr))

#define MMA_BF16(c, a, b0, b1) \
    asm volatile("mma.sync.aligned.m16n8k16.row.col.f32.bf16.bf16.f32 " \
        "{%0,%1,%2,%3}, {%4,%5,%6,%7}, {%8,%9}, {%0,%1,%2,%3};" \
        : "+f"((c)[0]), "+f"((c)[1]), "+f"((c)[2]), "+f"((c)[3]) \
        : "r"((a)[0]), "r"((a)[1]), "r"((a)[2]), "r"((a)[3]), "r"(b0), "r"(b1))

__device__ __forceinline__ uint32_t bfbits(float x) {
    return (uint32_t)__bfloat16_as_ushort(__float2bfloat16_rn(x));
}

// ---------------------------------------------------------------------------
// Edge binning (once per call, reused by all 4 layers). bin = (src>>7)*12+etype
// ---------------------------------------------------------------------------
__global__ void zero_count_kernel() {
    int i = blockIdx.x * blockDim.x + threadIdx.x;
    if (i < NBINS) g_count[i] = 0;
}

__global__ void hist_kernel(const int* __restrict__ src, const int* __restrict__ ety) {
    int e = blockIdx.x * blockDim.x + threadIdx.x;
    if (e >= NEDGES) return;
    atomicAdd(&g_count[(src[e] >> 7) * NREL + ety[e]], 1);
}

__global__ __launch_bounds__(1024) void scan_kernel() {
    __shared__ int sums[1024];
    const int tid = threadIdx.x;
    const int per = (NBINS + 1023) / 1024;   // 10
    int local[16];
    int s = 0;
    for (int j = 0; j < per; j++) {
        int idx = tid * per + j;
        local[j] = s;
        if (idx < NBINS) s += g_count[idx];
    }
    sums[tid] = s;
    __syncthreads();
    for (int off = 1; off < 1024; off <<= 1) {
        int v = (tid >= off) ? sums[tid - off] : 0;
        __syncthreads();
        sums[tid] += v;
        __syncthreads();
    }
    int pre = tid ? sums[tid - 1] : 0;
    for (int j = 0; j < per; j++) {
        int idx = tid * per + j;
        if (idx < NBINS) { g_binoff[idx] = pre + local[j]; g_cursor[idx] = pre + local[j]; }
    }
    if (tid == 0) g_binoff[NBINS] = sums[1023];
}

__global__ void sort_kernel(const int* __restrict__ src, const int* __restrict__ dst,
                            const int* __restrict__ ety) {
    int e = blockIdx.x * blockDim.x + threadIdx.x;
    if (e >= NEDGES) return;
    int s = src[e];
    int bin = (s >> 7) * NREL + ety[e];
    int pos = atomicAdd(&g_cursor[bin], 1);
    g_sorted[pos] = ((s & 127) << 17) | dst[e];
}

// ---------------------------------------------------------------------------
// zero agg
// ---------------------------------------------------------------------------
template<int DOUT>
__global__ void zero_agg_kernel(float* __restrict__ agg) {
    int i = blockIdx.x * blockDim.x + threadIdx.x;
    if (i < NNODES * (DOUT / 4))
        ((float4*)agg)[i] = make_float4(0.f, 0.f, 0.f, 0.f);
}

// ---------------------------------------------------------------------------
// prep_act: fp32 [N, DIN] -> bf16 [NPAD, 2*DIN] = [hi | lo]; optional relu(x+b).
// ---------------------------------------------------------------------------
template<int DIN, bool RELU>
__global__ __launch_bounds__(256) void prep_act_kernel(
    const float* __restrict__ in, const float* __restrict__ bias,
    __nv_bfloat16* __restrict__ out)
{
    constexpr int KP = 2 * DIN;
    int idx = blockIdx.x * 256 + threadIdx.x;
    if (idx >= NPAD * (DIN / 4)) return;
    int n  = idx / (DIN / 4);
    int k0 = (idx % (DIN / 4)) * 4;
    float4 v = make_float4(0.f, 0.f, 0.f, 0.f);
    if (n < NNODES) {
        v = __ldg((const float4*)(in + (size_t)n * DIN + k0));
        if (RELU) {
            float4 bv = __ldg((const float4*)(bias + k0));
            v.x = fmaxf(v.x + bv.x, 0.f); v.y = fmaxf(v.y + bv.y, 0.f);
            v.z = fmaxf(v.z + bv.z, 0.f); v.w = fmaxf(v.w + bv.w, 0.f);
        }
    }
    float xs[4] = {v.x, v.y, v.z, v.w};
    uint32_t hb[4], lb[4];
    #pragma unroll
    for (int j = 0; j < 4; j++) {
        __nv_bfloat16 h = __float2bfloat16_rn(xs[j]);
        hb[j] = (uint32_t)__bfloat16_as_ushort(h);
        lb[j] = bfbits(xs[j] - __bfloat162float(h));
    }
    *(uint2*)(out + (size_t)n * KP + k0) =
        make_uint2(hb[0] | (hb[1] << 16), hb[2] | (hb[3] << 16));
    *(uint2*)(out + (size_t)n * KP + DIN + k0) =
        make_uint2(lb[0] | (lb[1] << 16), lb[2] | (lb[3] << 16));
}

// ---------------------------------------------------------------------------
// prep_w: W [R, DIN, DOUT] + L -> bf16 [NMAT][2*DIN][DOUT], rows [hi | lo].
// ---------------------------------------------------------------------------
template<int DIN, int DOUT>
__global__ __launch_bounds__(256) void prep_w_kernel(
    const float* __restrict__ W, const float* __restrict__ L,
    __nv_bfloat16* __restrict__ out)
{
    int idx = blockIdx.x * 256 + threadIdx.x;
    if (idx >= NMAT * DIN * (DOUT / 4)) return;
    int m   = idx / (DIN * (DOUT / 4));
    int rem = idx % (DIN * (DOUT / 4));
    int k   = rem / (DOUT / 4);
    int n0  = (rem % (DOUT / 4)) * 4;
    const float* srcp = (m < NREL) ? (W + (size_t)m * DIN * DOUT) : L;
    float4 v = __ldg((const float4*)(srcp + (size_t)k * DOUT + n0));
    float xs[4] = {v.x, v.y, v.z, v.w};
    uint32_t hb[4], lb[4];
    #pragma unroll
    for (int j = 0; j < 4; j++) {
        __nv_bfloat16 h = __float2bfloat16_rn(xs[j]);
        hb[j] = (uint32_t)__bfloat16_as_ushort(h);
        lb[j] = bfbits(xs[j] - __bfloat162float(h));
    }
    __nv_bfloat16* base = out + (size_t)m * (2 * DIN) * DOUT;
    *(uint2*)(base + (size_t)k * DOUT + n0) =
        make_uint2(hb[0] | (hb[1] << 16), hb[2] | (hb[3] << 16));
    *(uint2*)(base + (size_t)(DIN + k) * DOUT + n0) =
        make_uint2(lb[0] | (lb[1] << 16), lb[2] | (lb[3] << 16));
}

// ---------------------------------------------------------------------------
// Fused GEMM + scatter. Per 128-node tile, for r = 0..12:
//   ttile = Ah*Wh + Ah*Wl + Al*Wh  (held in smem)
//   r<12 : for edges in bin(tile,r): agg[dst] += ttile[srcloc]   (float4 RED)
//   r==12: agg[tile nodes]         += ttile (self-loop)
// W single-buffered; W[r+1] prefetch overlaps the scatter of r.
// ---------------------------------------------------------------------------
template<int DIN, int DOUT>
__global__ __launch_bounds__(256) void fused_kernel(
    const __nv_bfloat16* __restrict__ aimg,   // [NPAD][2*DIN]
    const __nv_bfloat16* __restrict__ wimg,   // [NMAT][2*DIN][DOUT]
    float* __restrict__ agg)
{
    constexpr int KP      = 2 * DIN;
    constexpr int KC16    = DIN / 16;
    constexpr int NCH     = 3 * KC16;
    constexpr int LDA     = KP + 8;
    constexpr int LDW     = DOUT + 8;
    constexpr int A_BYTES = 128 * LDA * 2;
    constexpr int W_BYTES = KP * LDW * 2;
    constexpr int TSTR    = DOUT + 4;           // floats
    constexpr int NTILES  = DOUT / 16;

    extern __shared__ unsigned char sm[];
    const uint32_t smb = smem_u32(sm);
    const uint32_t wsm = smb + A_BYTES;
    float* tt = (float*)(sm + A_BYTES + W_BYTES);

    const int tid  = threadIdx.x;
    const int wid  = tid >> 5;
    const int lane = tid & 31;
    const int tile = blockIdx.x;
    const int m0   = (wid & 3) * 32;
    const int n0   = (wid >> 2) * (DOUT / 2);

    // Load A tile + W[0]
    const __nv_bfloat16* ga = aimg + (size_t)tile * 128 * KP;
    for (int i = tid; i < 128 * (KP / 8); i += 256) {
        int rr = i / (KP / 8), j = (i % (KP / 8)) * 8;
        CPASYNC16(smb + (rr * LDA + j) * 2, ga + (size_t)rr * KP + j);
    }
    for (int i = tid; i < KP * (DOUT / 8); i += 256) {
        int rr = i / (DOUT / 8), j = (i % (DOUT / 8)) * 8;
        CPASYNC16(wsm + (rr * LDW + j) * 2, wimg + (size_t)rr * DOUT + j);
    }
    CPASYNC_COMMIT();

    for (int r = 0; r < NMAT; ++r) {
        CPASYNC_WAIT0();
        __syncthreads();

        // ---- GEMM into registers ----
        float acc[2][NTILES][4];
        #pragma unroll
        for (int mt = 0; mt < 2; mt++)
            #pragma unroll
            for (int nt = 0; nt < NTILES; nt++) {
                acc[mt][nt][0] = 0.f; acc[mt][nt][1] = 0.f;
                acc[mt][nt][2] = 0.f; acc[mt][nt][3] = 0.f;
            }
        #pragma unroll
        for (int c = 0; c < NCH; ++c) {
            const int seg  = c / KC16;
            const int kk   = (c % KC16) * 16;
            const int aoff = (seg == 2 ? DIN : 0) + kk;
            const int wrow = (seg == 1 ? DIN : 0) + kk;
            uint32_t a[2][4];
            #pragma unroll
            for (int mt = 0; mt < 2; mt++) {
                uint32_t addr = smb +
                    (uint32_t)(((m0 + mt * 16 + (lane & 15)) * LDA + aoff) * 2) +
                    (uint32_t)((lane >> 4) * 16);
                LDSM_X4(a[mt][0], a[mt][1], a[mt][2], a[mt][3], addr);
            }
            uint32_t b[NTILES][2];
            #pragma unroll
            for (int np = 0; np < NTILES / 2; np++) {
                uint32_t addr = wsm +
                    (uint32_t)(((wrow + (lane & 15)) * LDW + n0 + np * 16) * 2) +
                    (uint32_t)((lane >> 4) * 16);
                LDSM_X4_T(b[2 * np][0], b[2 * np][1],
                          b[2 * np + 1][0], b[2 * np + 1][1], addr);
            }
            #pragma unroll
            for (int mt = 0; mt < 2; mt++)
                #pragma unroll
                for (int nt = 0; nt < NTILES; nt++)
                    MMA_BF16(acc[mt][nt], a[mt], b[nt][0], b[nt][1]);
        }
        __syncthreads();   // all warps done reading W smem

        // ---- prefetch W[r+1] into the (now free) W buffer ----
        if (r + 1 < NMAT) {
            const __nv_bfloat16* gw = wimg + (size_t)(r + 1) * KP * DOUT;
            for (int i = tid; i < KP * (DOUT / 8); i += 256) {
                int rr = i / (DOUT / 8), j = (i % (DOUT / 8)) * 8;
                CPASYNC16(wsm + (rr * LDW + j) * 2, gw + (size_t)rr * DOUT + j);
            }
            CPASYNC_COMMIT();
        }

        // ---- write result tile to smem ----
        #pragma unroll
        for (int mt = 0; mt < 2; mt++) {
            int row = m0 + mt * 16 + (lane >> 2);
            float* p = tt + row * TSTR + n0 + (lane & 3) * 2;
            #pragma unroll
            for (int nt = 0; nt < NTILES; nt++) {
                p[nt * 8]     = acc[mt][nt][0];
                p[nt * 8 + 1] = acc[mt][nt][1];
                p[8 * TSTR + nt * 8]     = acc[mt][nt][2];
                p[8 * TSTR + nt * 8 + 1] = acc[mt][nt][3];
            }
        }
        __syncthreads();

        // ---- scatter ----
        if (r < NREL) {
            const int bin   = tile * NREL + r;
            const int start = g_binoff[bin];
            const int end   = g_binoff[bin + 1];
            for (int e = start + wid; e < end; e += 8) {
                int packed = __ldg(&g_sorted[e]);
                int srcloc = packed >> 17;
                int d      = packed & 0x1FFFF;
                if (lane < DOUT / 4) {
                    float4 v = *(const float4*)(tt + srcloc * TSTR + lane * 4);
                    atomicAdd(((float4*)(agg + (size_t)d * DOUT)) + lane, v);
                }
            }
        } else {
            // self-loop: add tile's own rows
            #pragma unroll 1
            for (int i = wid * 16; i < wid * 16 + 16; i++) {
                int n = tile * 128 + i;
                if (n >= NNODES) break;
                if (lane < DOUT / 4) {
                    float4 v = *(const float4*)(tt + i * TSTR + lane * 4);
                    atomicAdd(((float4*)(agg + (size_t)n * DOUT)) + lane, v);
                }
            }
        }
        __syncthreads();   // ttile free for next r
    }
}

// ---------------------------------------------------------------------------
// Final dense: hd[n,:2] = relu(agg[n,:64] + b3) @ Wd + bd
// ---------------------------------------------------------------------------
__global__ __launch_bounds__(256) void dense_kernel(
    const float* __restrict__ agg, const float* __restrict__ b3,
    const float* __restrict__ Wd, const float* __restrict__ bd,
    float* __restrict__ hd, int nNodes)
{
    int n = blockIdx.x * blockDim.x + threadIdx.x;
    if (n >= nNodes) return;
    float a0 = bd[0], a1 = bd[1];
    const float4* row = (const float4*)(agg + (size_t)n * 64);
    #pragma unroll
    for (int kq = 0; kq < 16; kq++) {
        float4 v  = __ldg(row + kq);
        float4 bb = __ldg((const float4*)(b3 + kq * 4));
        float x; int k = kq * 4;
        x = fmaxf(v.x + bb.x, 0.f); a0 += x * Wd[(k + 0) * 2]; a1 += x * Wd[(k + 0) * 2 + 1];
        x = fmaxf(v.y + bb.y, 0.f); a0 += x * Wd[(k + 1) * 2]; a1 += x * Wd[(k + 1) * 2 + 1];
        x = fmaxf(v.z + bb.z, 0.f); a0 += x * Wd[(k + 2) * 2]; a1 += x * Wd[(k + 2) * 2 + 1];
        x = fmaxf(v.w + bb.w, 0.f); a0 += x * Wd[(k + 3) * 2]; a1 += x * Wd[(k + 3) * 2 + 1];
    }
    hd[(size_t)n * 2]     = a0;
    hd[(size_t)n * 2 + 1] = a1;
}

__global__ void gather_kernel(const int* __restrict__ ei,
                              const float* __restrict__ hd,
                              float* __restrict__ out, int P)
{
    int p = blockIdx.x * blockDim.x + threadIdx.x;
    if (p >= P) return;
    int4 idx = ((const int4*)ei)[p];
    float2 a = ((const float2*)hd)[idx.x];
    float2 b = ((const float2*)hd)[idx.y];
    float2 c = ((const float2*)hd)[idx.z];
    float2 d = ((const float2*)hd)[idx.w];
    out[(size_t)p * 2]             = (a.x + b.x) * 0.5f;
    out[(size_t)p * 2 + 1]         = (a.y + b.y) * 0.5f;
    out[(size_t)2 * P + p * 2]     = (c.x + d.x) * 0.5f;
    out[(size_t)2 * P + p * 2 + 1] = (c.y + d.y) * 0.5f;
}

// ---------------------------------------------------------------------------
// Host launcher
// ---------------------------------------------------------------------------
extern "C" void kernel_launch(void* const* d_in, const int* in_sizes, int n_in,
                              void* d_out, int out_size)
{
    const float* h   = (const float*)d_in[0];
    const int*   src = (const int*)d_in[1];
    const int*   dst = (const int*)d_in[2];
    const int*   ety = (const int*)d_in[3];
    const int*   ei  = (const int*)d_in[4];
    const float* W0 = (const float*)d_in[5],  *L0 = (const float*)d_in[6],  *b0 = (const float*)d_in[7];
    const float* W1 = (const float*)d_in[8],  *L1 = (const float*)d_in[9],  *b1 = (const float*)d_in[10];
    const float* W2 = (const float*)d_in[11], *L2 = (const float*)d_in[12], *b2 = (const float*)d_in[13];
    const float* W3 = (const float*)d_in[14], *L3 = (const float*)d_in[15], *b3 = (const float*)d_in[16];
    const float* Wd = (const float*)d_in[17], *bd = (const float*)d_in[18];
    float* out = (float*)d_out;

    float *agg, *hd;
    __nv_bfloat16 *as, *ws;
    cudaGetSymbolAddress((void**)&agg, g_agg);
    cudaGetSymbolAddress((void**)&hd,  g_hd);
    cudaGetSymbolAddress((void**)&as,  g_asplit);
    cudaGetSymbolAddress((void**)&ws,  g_wsplit);

    // smem: A + W(single) + ttile(fp32, padded)
    const int SM_16_128  = 128 * 40 * 2  + 32 * 136 * 2  + 128 * 132 * 4;   //  86528
    const int SM_128_128 = 128 * 264 * 2 + 256 * 136 * 2 + 128 * 132 * 4;   // 204800
    const int SM_128_64  = 128 * 264 * 2 + 256 * 72 * 2  + 128 * 68 * 4;    // 139264
    cudaFuncSetAttribute(fused_kernel<16, 128>,  cudaFuncAttributeMaxDynamicSharedMemorySize, SM_16_128);
    cudaFuncSetAttribute(fused_kernel<128, 128>, cudaFuncAttributeMaxDynamicSharedMemorySize, SM_128_128);
    cudaFuncSetAttribute(fused_kernel<128, 64>,  cudaFuncAttributeMaxDynamicSharedMemorySize, SM_128_64);

    // ---- edge binning (once) ----
    zero_count_kernel<<<(NBINS + 255) / 256, 256>>>();
    hist_kernel<<<(NEDGES + 255) / 256, 256>>>(src, ety);
    scan_kernel<<<1, 1024>>>();
    sort_kernel<<<(NEDGES + 255) / 256, 256>>>(src, dst, ety);

    // ---- Layer 0: 16 -> 128 ----
    prep_w_kernel<16, 128><<<(NMAT * 16 * 32 + 255) / 256, 256>>>(W0, L0, ws);
    prep_act_kernel<16, false><<<(NPAD * 4 + 255) / 256, 256>>>(h, nullptr, as);
    zero_agg_kernel<128><<<(NNODES * 32 + 255) / 256, 256>>>(agg);
    fused_kernel<16, 128><<<NT, 256, SM_16_128>>>(as, ws, agg);

    // ---- Layer 1: 128 -> 128 ----
    prep_w_kernel<128, 128><<<(NMAT * 128 * 32 + 255) / 256, 256>>>(W1, L1, ws);
    prep_act_kernel<128, true><<<(NPAD * 32 + 255) / 256, 256>>>(agg, b0, as);
    zero_agg_kernel<128><<<(NNODES * 32 + 255) / 256, 256>>>(agg);
    fused_kernel<128, 128><<<NT, 256, SM_128_128>>>(as, ws, agg);

    // ---- Layer 2: 128 -> 128 ----
    prep_w_kernel<128, 128><<<(NMAT * 128 * 32 + 255) / 256, 256>>>(W2, L2, ws);
    prep_act_kernel<128, true><<<(NPAD * 32 + 255) / 256, 256>>>(agg, b1, as);
    zero_agg_kernel<128><<<(NNODES * 32 + 255) / 256, 256>>>(agg);
    fused_kernel<128, 128><<<NT, 256, SM_128_128>>>(as, ws, agg);

    // ---- Layer 3: 128 -> 64 ----
    prep_w_kernel<128, 64><<<(NMAT * 128 * 16 + 255) / 256, 256>>>(W3, L3, ws);
    prep_act_kernel<128, true><<<(NPAD * 32 + 255) / 256, 256>>>(agg, b2, as);
    zero_agg_kernel<64><<<(NNODES * 16 + 255) / 256, 256>>>(agg);
    fused_kernel<128, 64><<<NT, 256, SM_128_64>>>(as, ws, agg);

    // ---- Final dense + pair gather ----
    dense_kernel<<<(NNODES + 255) / 256, 256>>>(agg, b3, Wd, bd, hd, NNODES);
    gather_kernel<<<(NPAIR + 255) / 256, 256>>>(ei, hd, out, NPAIR);
}